// round 1
// baseline (speedup 1.0000x reference)
#include <cuda_runtime.h>
#include <math.h>

// Problem constants (fixed by the reference)
constexpr int Hc = 512, Wc = 512;
constexpr int Bc = 2, Gc = 4, Fc = 9, Cc = 3;
constexpr int Nn = Hc * Wc;

// Tiling
constexpr int TILE = 32;           // output tile
constexpr int RF   = TILE + 4;     // 36: fM region (2-pixel halo)
constexpr int RD   = TILE + 2;     // 34: deg/dinv/sig/ew region (1-pixel halo)
constexpr int FSTR = 10;           // padded per-pixel stride for fM (float2-friendly, conflict-free)

// SMEM layout (floats)
constexpr int OFF_F    = 0;
constexpr int SZ_F     = RF * RF * FSTR;          // 12960
constexpr int OFF_EW   = OFF_F + SZ_F;
constexpr int SZ_EW    = RD * RD * 9;             // 10404
constexpr int OFF_DINV = OFF_EW + SZ_EW;
constexpr int SZ_DINV  = RD * RD;                 // 1156
constexpr int OFF_SIG  = OFF_DINV + SZ_DINV;
constexpr int SZ_SIG   = 3 * RD * RD;             // 3468
constexpr int SM_FLOATS = OFF_SIG + SZ_SIG;       // 27988
constexpr int SMEM_BYTES = SM_FLOATS * 4;         // 111952 B -> 2 blocks/SM

__constant__ float cM[Gc * Fc * Fc];              // multiM, copied in at launch

__device__ __forceinline__ float dot9(const float a[9], const float* __restrict__ q) {
    const float2* q2 = reinterpret_cast<const float2*>(q);
    float2 p01 = q2[0], p23 = q2[1], p45 = q2[2], p67 = q2[3];
    float s = a[0] * p01.x;
    s = fmaf(a[1], p01.y, s);
    s = fmaf(a[2], p23.x, s);
    s = fmaf(a[3], p23.y, s);
    s = fmaf(a[4], p45.x, s);
    s = fmaf(a[5], p45.y, s);
    s = fmaf(a[6], p67.x, s);
    s = fmaf(a[7], p67.y, s);
    s = fmaf(a[8], q[8], s);
    return s;
}

__global__ void __launch_bounds__(256, 2)
glr_fused_kernel(const float* __restrict__ img,
                 const float* __restrict__ sig,
                 float* __restrict__ out)
{
    extern __shared__ float sm[];
    float* __restrict__ sF    = sm + OFF_F;
    float* __restrict__ sEw   = sm + OFF_EW;
    float* __restrict__ sDinv = sm + OFF_DINV;
    float* __restrict__ sSig  = sm + OFF_SIG;

    const int tid = threadIdx.x;
    const int bg  = blockIdx.z;            // b*G + g
    const int g   = bg & (Gc - 1);
    const int x0  = blockIdx.x * TILE;
    const int y0  = blockIdx.y * TILE;

    const float* __restrict__ imgbg = img + (size_t)bg * Fc * Nn;
    const float* __restrict__ sigbg = sig + (size_t)bg * Cc * Nn;
    const float* __restrict__ m     = cM + g * 81;

    // ---------------- Phase 1: fM over 36x36 halo region ----------------
    for (int idx = tid; idx < RF * RF; idx += 256) {
        const int ly = idx / RF;
        const int lx = idx - ly * RF;
        const int gy = y0 - 2 + ly;
        const int gx = x0 - 2 + lx;
        float* __restrict__ dst = sF + idx * FSTR;
        if ((unsigned)gy < (unsigned)Hc && (unsigned)gx < (unsigned)Wc) {
            const int p = gy * Wc + gx;
            float x[9];
            float ss = 0.f;
            #pragma unroll
            for (int f = 0; f < 9; f++) {
                x[f] = __ldg(imgbg + (size_t)f * Nn + p);
                ss = fmaf(x[f], x[f], ss);
            }
            const float inv = 1.0f / fmaxf(sqrtf(ss), 1e-12f);
            float acc[9];
            #pragma unroll
            for (int v = 0; v < 9; v++) acc[v] = x[0] * m[v];
            #pragma unroll
            for (int c = 1; c < 9; c++) {
                #pragma unroll
                for (int v = 0; v < 9; v++) acc[v] = fmaf(x[c], m[c * 9 + v], acc[v]);
            }
            float2* d2 = reinterpret_cast<float2*>(dst);
            d2[0] = make_float2(acc[0] * inv, acc[1] * inv);
            d2[1] = make_float2(acc[2] * inv, acc[3] * inv);
            d2[2] = make_float2(acc[4] * inv, acc[5] * inv);
            d2[3] = make_float2(acc[6] * inv, acc[7] * inv);
            dst[8] = acc[8] * inv;
        } else {
            float2* d2 = reinterpret_cast<float2*>(dst);
            d2[0] = make_float2(0.f, 0.f);
            d2[1] = make_float2(0.f, 0.f);
            d2[2] = make_float2(0.f, 0.f);
            d2[3] = make_float2(0.f, 0.f);
            dst[8] = 0.f;
        }
    }
    __syncthreads();

    // ------- Phase 2: ew (all 9 dirs), deg -> dinv, and sig load over 34x34 -------
    for (int idx = tid; idx < RD * RD; idx += 256) {
        const int ly = idx / RD;
        const int lx = idx - ly * RD;
        const int gy = y0 - 1 + ly;
        const int gx = x0 - 1 + lx;
        const bool inb = ((unsigned)gy < (unsigned)Hc) && ((unsigned)gx < (unsigned)Wc);

        // signals into smem (0 for OOB halo; multiplied by ew==0 later)
        {
            const int p = gy * Wc + gx;
            #pragma unroll
            for (int c = 0; c < 3; c++)
                sSig[c * (RD * RD) + idx] = inb ? __ldg(sigbg + (size_t)c * Nn + p) : 0.f;
        }

        float ew[9];
        float dinv = 0.f;
        if (inb) {
            const float* __restrict__ pf = sF + ((ly + 1) * RF + (lx + 1)) * FSTR;
            float a[9];
            {
                const float2* a2 = reinterpret_cast<const float2*>(pf);
                float2 t0 = a2[0], t1 = a2[1], t2 = a2[2], t3 = a2[3];
                a[0] = t0.x; a[1] = t0.y; a[2] = t1.x; a[3] = t1.y;
                a[4] = t2.x; a[5] = t2.y; a[6] = t3.x; a[7] = t3.y;
                a[8] = pf[8];
            }
            float deg = 0.f;
            #pragma unroll
            for (int t = 0; t < 9; t++) {
                const int dy = t / 3 - 1;
                const int dx = t % 3 - 1;
                const int qy = gy + dy;
                const int qx = gx + dx;
                float e = 0.f;
                if ((unsigned)qy < (unsigned)Hc && (unsigned)qx < (unsigned)Wc) {
                    float s = dot9(a, pf + (dy * RF + dx) * FSTR);
                    s = fminf(fmaxf(s, -10.f), 10.f);
                    e = __expf(s);
                }
                ew[t] = e;
                deg += e;
            }
            dinv = rsqrtf(deg);  // deg >= exp(0) = 1 (self-edge), always safe
        } else {
            #pragma unroll
            for (int t = 0; t < 9; t++) ew[t] = 0.f;
        }
        #pragma unroll
        for (int t = 0; t < 9; t++) sEw[idx * 9 + t] = ew[t];
        sDinv[idx] = dinv;
    }
    __syncthreads();

    // ---------------- Phase 3: normalized aggregation + output ----------------
    float* __restrict__ outbg = out + (size_t)bg * Cc * Nn;
    for (int idx = tid; idx < TILE * TILE; idx += 256) {
        const int ly = idx >> 5;
        const int lx = idx & 31;
        const int e = (ly + 1) * RD + (lx + 1);
        const float dp = sDinv[e];
        float a0 = 0.f, a1 = 0.f, a2 = 0.f;
        #pragma unroll
        for (int t = 0; t < 9; t++) {
            const int dy = t / 3 - 1;
            const int dx = t % 3 - 1;
            const int ne = e + dy * RD + dx;
            const float w = dp * sEw[e * 9 + t] * sDinv[ne];
            a0 = fmaf(sSig[ne], w, a0);
            a1 = fmaf(sSig[RD * RD + ne], w, a1);
            a2 = fmaf(sSig[2 * RD * RD + ne], w, a2);
        }
        const int gy = y0 + ly;
        const int gx = x0 + lx;
        const int p = gy * Wc + gx;
        outbg[p]             = sSig[e]              - a0;
        outbg[Nn + p]        = sSig[RD * RD + e]    - a1;
        outbg[2 * Nn + p]    = sSig[2 * RD * RD + e] - a2;
    }
}

extern "C" void kernel_launch(void* const* d_in, const int* in_sizes, int n_in,
                              void* d_out, int out_size) {
    const float* img = (const float*)d_in[0];  // (B,G,F,H,W)
    const float* sig = (const float*)d_in[1];  // (B,G,C,H,W)
    const float* M   = (const float*)d_in[2];  // (G,F,F)
    // d_in[3..5] = edges/order/order_inverse: structurally redundant (3x3 stencil), unused.
    float* out = (float*)d_out;

    cudaFuncSetAttribute(glr_fused_kernel,
                         cudaFuncAttributeMaxDynamicSharedMemorySize, SMEM_BYTES);
    cudaMemcpyToSymbolAsync(cM, M, Gc * Fc * Fc * sizeof(float), 0,
                            cudaMemcpyDeviceToDevice, 0);

    dim3 grid(Wc / TILE, Hc / TILE, Bc * Gc);
    glr_fused_kernel<<<grid, 256, SMEM_BYTES>>>(img, sig, out);
}

// round 2
// speedup vs baseline: 1.1931x; 1.1931x over previous
#include <cuda_runtime.h>
#include <math.h>

// Problem constants (fixed by the reference)
constexpr int Hc = 512, Wc = 512;
constexpr int Bc = 2, Gc = 4, Fc = 9, Cc = 3;
constexpr int Nn = Hc * Wc;

// Tiling
constexpr int TILE = 32;           // output tile
constexpr int RF   = TILE + 4;     // 36: fM region (2-pixel halo)
constexpr int RD   = TILE + 2;     // 34: deg/dinv/sig/ew region (1-pixel halo)
constexpr int FSTR = 10;           // padded per-pixel stride for fM (float2-friendly, conflict-free)

constexpr int NTHREADS = 512;

// SMEM layout (floats)
constexpr int OFF_F    = 0;
constexpr int SZ_F     = RF * RF * FSTR;          // 12960
constexpr int OFF_EW   = OFF_F + SZ_F;
constexpr int SZ_EW    = RD * RD * 9;             // 10404
constexpr int OFF_DINV = OFF_EW + SZ_EW;
constexpr int SZ_DINV  = RD * RD;                 // 1156
constexpr int OFF_SIG  = OFF_DINV + SZ_DINV;
constexpr int SZ_SIG   = 3 * RD * RD;             // 3468
constexpr int SM_FLOATS = OFF_SIG + SZ_SIG;       // 27988
constexpr int SMEM_BYTES = SM_FLOATS * 4;         // 111952 B -> 2 blocks/SM (with 512 thr = 32 warps)

__constant__ float cM[Gc * Fc * Fc];              // multiM, copied in at launch

__device__ __forceinline__ float dot9(const float a[9], const float* __restrict__ q) {
    const float2* q2 = reinterpret_cast<const float2*>(q);
    float2 p01 = q2[0], p23 = q2[1], p45 = q2[2], p67 = q2[3];
    float s = a[0] * p01.x;
    s = fmaf(a[1], p01.y, s);
    s = fmaf(a[2], p23.x, s);
    s = fmaf(a[3], p23.y, s);
    s = fmaf(a[4], p45.x, s);
    s = fmaf(a[5], p45.y, s);
    s = fmaf(a[6], p67.x, s);
    s = fmaf(a[7], p67.y, s);
    s = fmaf(a[8], q[8], s);
    return s;
}

__global__ void __launch_bounds__(NTHREADS, 2)
glr_fused_kernel(const float* __restrict__ img,
                 const float* __restrict__ sig,
                 float* __restrict__ out)
{
    extern __shared__ float sm[];
    float* __restrict__ sF    = sm + OFF_F;
    float* __restrict__ sEw   = sm + OFF_EW;
    float* __restrict__ sDinv = sm + OFF_DINV;
    float* __restrict__ sSig  = sm + OFF_SIG;

    const int tid = threadIdx.x;
    const int bg  = blockIdx.z;            // b*G + g
    const int g   = bg & (Gc - 1);
    const int x0  = blockIdx.x * TILE;
    const int y0  = blockIdx.y * TILE;

    const float* __restrict__ imgbg = img + (size_t)bg * Fc * Nn;
    const float* __restrict__ sigbg = sig + (size_t)bg * Cc * Nn;
    const float* __restrict__ m     = cM + g * 81;

    // ---------------- Phase 1: fM over 36x36 halo region ----------------
    for (int idx = tid; idx < RF * RF; idx += NTHREADS) {
        const int ly = idx / RF;
        const int lx = idx - ly * RF;
        const int gy = y0 - 2 + ly;
        const int gx = x0 - 2 + lx;
        float* __restrict__ dst = sF + idx * FSTR;
        if ((unsigned)gy < (unsigned)Hc && (unsigned)gx < (unsigned)Wc) {
            const int p = gy * Wc + gx;
            float x[9];
            float ss = 0.f;
            #pragma unroll
            for (int f = 0; f < 9; f++) {
                x[f] = __ldg(imgbg + (size_t)f * Nn + p);
                ss = fmaf(x[f], x[f], ss);
            }
            const float inv = 1.0f / fmaxf(sqrtf(ss), 1e-12f);
            float acc[9];
            #pragma unroll
            for (int v = 0; v < 9; v++) acc[v] = x[0] * m[v];
            #pragma unroll
            for (int c = 1; c < 9; c++) {
                #pragma unroll
                for (int v = 0; v < 9; v++) acc[v] = fmaf(x[c], m[c * 9 + v], acc[v]);
            }
            float2* d2 = reinterpret_cast<float2*>(dst);
            d2[0] = make_float2(acc[0] * inv, acc[1] * inv);
            d2[1] = make_float2(acc[2] * inv, acc[3] * inv);
            d2[2] = make_float2(acc[4] * inv, acc[5] * inv);
            d2[3] = make_float2(acc[6] * inv, acc[7] * inv);
            dst[8] = acc[8] * inv;
        } else {
            float2* d2 = reinterpret_cast<float2*>(dst);
            d2[0] = make_float2(0.f, 0.f);
            d2[1] = make_float2(0.f, 0.f);
            d2[2] = make_float2(0.f, 0.f);
            d2[3] = make_float2(0.f, 0.f);
            dst[8] = 0.f;
        }
    }
    __syncthreads();

    // ------- Phase 2: ew (all 9 dirs), deg -> dinv, and sig load over 34x34 -------
    for (int idx = tid; idx < RD * RD; idx += NTHREADS) {
        const int ly = idx / RD;
        const int lx = idx - ly * RD;
        const int gy = y0 - 1 + ly;
        const int gx = x0 - 1 + lx;
        const bool inb = ((unsigned)gy < (unsigned)Hc) && ((unsigned)gx < (unsigned)Wc);

        // signals into smem (0 for OOB halo; multiplied by ew==0 later)
        {
            const int p = gy * Wc + gx;
            #pragma unroll
            for (int c = 0; c < 3; c++)
                sSig[c * (RD * RD) + idx] = inb ? __ldg(sigbg + (size_t)c * Nn + p) : 0.f;
        }

        float ew[9];
        float dinv = 0.f;
        if (inb) {
            const float* __restrict__ pf = sF + ((ly + 1) * RF + (lx + 1)) * FSTR;
            float a[9];
            {
                const float2* a2 = reinterpret_cast<const float2*>(pf);
                float2 t0 = a2[0], t1 = a2[1], t2 = a2[2], t3 = a2[3];
                a[0] = t0.x; a[1] = t0.y; a[2] = t1.x; a[3] = t1.y;
                a[4] = t2.x; a[5] = t2.y; a[6] = t3.x; a[7] = t3.y;
                a[8] = pf[8];
            }
            float deg = 0.f;
            #pragma unroll
            for (int t = 0; t < 9; t++) {
                const int dy = t / 3 - 1;
                const int dx = t % 3 - 1;
                const int qy = gy + dy;
                const int qx = gx + dx;
                float e = 0.f;
                if ((unsigned)qy < (unsigned)Hc && (unsigned)qx < (unsigned)Wc) {
                    float s = dot9(a, pf + (dy * RF + dx) * FSTR);
                    s = fminf(fmaxf(s, -10.f), 10.f);
                    e = __expf(s);
                }
                ew[t] = e;
                deg += e;
            }
            dinv = rsqrtf(deg);  // deg >= exp(0) = 1 (self-edge), always safe
        } else {
            #pragma unroll
            for (int t = 0; t < 9; t++) ew[t] = 0.f;
        }
        #pragma unroll
        for (int t = 0; t < 9; t++) sEw[idx * 9 + t] = ew[t];
        sDinv[idx] = dinv;
    }
    __syncthreads();

    // ---------------- Phase 3: normalized aggregation + output ----------------
    float* __restrict__ outbg = out + (size_t)bg * Cc * Nn;
    for (int idx = tid; idx < TILE * TILE; idx += NTHREADS) {
        const int ly = idx >> 5;
        const int lx = idx & 31;
        const int e = (ly + 1) * RD + (lx + 1);
        const float dp = sDinv[e];
        float a0 = 0.f, a1 = 0.f, a2 = 0.f;
        #pragma unroll
        for (int t = 0; t < 9; t++) {
            const int dy = t / 3 - 1;
            const int dx = t % 3 - 1;
            const int ne = e + dy * RD + dx;
            const float w = dp * sEw[e * 9 + t] * sDinv[ne];
            a0 = fmaf(sSig[ne], w, a0);
            a1 = fmaf(sSig[RD * RD + ne], w, a1);
            a2 = fmaf(sSig[2 * RD * RD + ne], w, a2);
        }
        const int gy = y0 + ly;
        const int gx = x0 + lx;
        const int p = gy * Wc + gx;
        outbg[p]             = sSig[e]              - a0;
        outbg[Nn + p]        = sSig[RD * RD + e]    - a1;
        outbg[2 * Nn + p]    = sSig[2 * RD * RD + e] - a2;
    }
}

extern "C" void kernel_launch(void* const* d_in, const int* in_sizes, int n_in,
                              void* d_out, int out_size) {
    const float* img = (const float*)d_in[0];  // (B,G,F,H,W)
    const float* sig = (const float*)d_in[1];  // (B,G,C,H,W)
    const float* M   = (const float*)d_in[2];  // (G,F,F)
    // d_in[3..5] = edges/order/order_inverse: structurally redundant (3x3 stencil), unused.
    float* out = (float*)d_out;

    cudaFuncSetAttribute(glr_fused_kernel,
                         cudaFuncAttributeMaxDynamicSharedMemorySize, SMEM_BYTES);
    cudaMemcpyToSymbolAsync(cM, M, Gc * Fc * Fc * sizeof(float), 0,
                            cudaMemcpyDeviceToDevice, 0);

    dim3 grid(Wc / TILE, Hc / TILE, Bc * Gc);
    glr_fused_kernel<<<grid, NTHREADS, SMEM_BYTES>>>(img, sig, out);
}

// round 3
// speedup vs baseline: 1.3892x; 1.1644x over previous
#include <cuda_runtime.h>
#include <math.h>

// Problem constants (fixed by the reference)
constexpr int Hc = 512, Wc = 512;
constexpr int Bc = 2, Gc = 4, Fc = 9, Cc = 3;
constexpr int Nn = Hc * Wc;

// Tiling
constexpr int TILE = 32;           // output tile
constexpr int RF   = TILE + 4;     // 36: fM + ew region (2-pixel halo), offset -2
constexpr int RD   = TILE + 2;     // 34: dinv/sig region (1-pixel halo), offset -1
constexpr int FSTR = 10;           // padded per-pixel stride for fM

constexpr int NTHREADS = 512;

// SMEM layout (floats)
constexpr int OFF_F  = 0;
constexpr int SZ_F   = RF * RF * FSTR;     // 12960
constexpr int OFF_EW = OFF_F + SZ_F;       // 12960 (byte off 51840, 16B aligned)
constexpr int SZ_EW  = RF * RF * 5;        // 6480 (5 dirs: self,E,SW,S,SE)
constexpr int OFF_SD = OFF_EW + SZ_EW;     // 19440 (byte off 77760, 16B aligned)
constexpr int SZ_SD  = RD * RD * 4;        // 4624 (float4: sig0,sig1,sig2,dinv)
constexpr int SM_FLOATS = OFF_SD + SZ_SD;  // 24064
constexpr int SMEM_BYTES = SM_FLOATS * 4;  // 96256 B -> 2 blocks/SM

__constant__ float cM[Gc * Fc * Fc];

__device__ __forceinline__ float dot9(const float a[9], const float* __restrict__ q) {
    const float2* q2 = reinterpret_cast<const float2*>(q);
    float2 p01 = q2[0], p23 = q2[1], p45 = q2[2], p67 = q2[3];
    float s = a[0] * p01.x;
    s = fmaf(a[1], p01.y, s);
    s = fmaf(a[2], p23.x, s);
    s = fmaf(a[3], p23.y, s);
    s = fmaf(a[4], p45.x, s);
    s = fmaf(a[5], p45.y, s);
    s = fmaf(a[6], p67.x, s);
    s = fmaf(a[7], p67.y, s);
    s = fmaf(a[8], q[8], s);
    return s;
}

__device__ __forceinline__ float eclip(float s) {
    return __expf(fminf(fmaxf(s, -10.f), 10.f));
}

__global__ void __launch_bounds__(NTHREADS, 2)
glr_fused_kernel(const float* __restrict__ img,
                 const float* __restrict__ sig,
                 float* __restrict__ out)
{
    extern __shared__ float sm[];
    float*  __restrict__ sF  = sm + OFF_F;
    float*  __restrict__ sEw = sm + OFF_EW;
    float4* __restrict__ sSD = reinterpret_cast<float4*>(sm + OFF_SD);

    const int tid = threadIdx.x;
    const int bg  = blockIdx.z;
    const int g   = bg & (Gc - 1);
    const int x0  = blockIdx.x * TILE;
    const int y0  = blockIdx.y * TILE;

    const float* __restrict__ imgbg = img + (size_t)bg * Fc * Nn;
    const float* __restrict__ sigbg = sig + (size_t)bg * Cc * Nn;
    const float* __restrict__ m     = cM + g * 81;

    // ---------------- Phase 1: fM over 36x36 region ----------------
    for (int idx = tid; idx < RF * RF; idx += NTHREADS) {
        const int ry = idx / RF;
        const int rx = idx - ry * RF;
        const int gy = y0 - 2 + ry;
        const int gx = x0 - 2 + rx;
        float* __restrict__ dst = sF + idx * FSTR;
        if ((unsigned)gy < (unsigned)Hc && (unsigned)gx < (unsigned)Wc) {
            const int p = gy * Wc + gx;
            float x[9];
            float ss = 0.f;
            #pragma unroll
            for (int f = 0; f < 9; f++) {
                x[f] = __ldg(imgbg + (size_t)f * Nn + p);
                ss = fmaf(x[f], x[f], ss);
            }
            const float inv = 1.0f / fmaxf(sqrtf(ss), 1e-12f);
            float acc[9];
            #pragma unroll
            for (int v = 0; v < 9; v++) acc[v] = x[0] * m[v];
            #pragma unroll
            for (int c = 1; c < 9; c++) {
                #pragma unroll
                for (int v = 0; v < 9; v++) acc[v] = fmaf(x[c], m[c * 9 + v], acc[v]);
            }
            float2* d2 = reinterpret_cast<float2*>(dst);
            d2[0] = make_float2(acc[0] * inv, acc[1] * inv);
            d2[1] = make_float2(acc[2] * inv, acc[3] * inv);
            d2[2] = make_float2(acc[4] * inv, acc[5] * inv);
            d2[3] = make_float2(acc[6] * inv, acc[7] * inv);
            dst[8] = acc[8] * inv;
        } else {
            float2* d2 = reinterpret_cast<float2*>(dst);
            d2[0] = make_float2(0.f, 0.f);
            d2[1] = make_float2(0.f, 0.f);
            d2[2] = make_float2(0.f, 0.f);
            d2[3] = make_float2(0.f, 0.f);
            dst[8] = 0.f;
        }
    }
    __syncthreads();

    // ------- Phase 2a: 5-direction ew (self,E,SW,S,SE) over 36x36 -------
    // ew(p,q)=ew(q,p): northern/western dirs recovered by transpose later.
    for (int idx = tid; idx < RF * RF; idx += NTHREADS) {
        const int ry = idx / RF;
        const int rx = idx - ry * RF;
        const int gy = y0 - 2 + ry;
        const int gx = x0 - 2 + rx;
        const bool inb = ((unsigned)gy < (unsigned)Hc) && ((unsigned)gx < (unsigned)Wc);

        float e[5] = {0.f, 0.f, 0.f, 0.f, 0.f};
        if (inb) {
            const float* __restrict__ pf = sF + idx * FSTR;
            float a[9];
            {
                const float2* a2 = reinterpret_cast<const float2*>(pf);
                float2 t0 = a2[0], t1 = a2[1], t2 = a2[2], t3 = a2[3];
                a[0] = t0.x; a[1] = t0.y; a[2] = t1.x; a[3] = t1.y;
                a[4] = t2.x; a[5] = t2.y; a[6] = t3.x; a[7] = t3.y;
                a[8] = pf[8];
            }
            // self
            {
                float s = fmaf(a[0], a[0], 0.f);
                #pragma unroll
                for (int f = 1; f < 9; f++) s = fmaf(a[f], a[f], s);
                e[0] = eclip(s);
            }
            // E (0,+1)
            if (rx + 1 < RF && (unsigned)(gx + 1) < (unsigned)Wc)
                e[1] = eclip(dot9(a, pf + FSTR));
            // SW (+1,-1)
            if (ry + 1 < RF && rx - 1 >= 0 &&
                (unsigned)(gy + 1) < (unsigned)Hc && (unsigned)(gx - 1) < (unsigned)Wc)
                e[2] = eclip(dot9(a, pf + (RF - 1) * FSTR));
            // S (+1,0)
            if (ry + 1 < RF && (unsigned)(gy + 1) < (unsigned)Hc)
                e[3] = eclip(dot9(a, pf + RF * FSTR));
            // SE (+1,+1)
            if (ry + 1 < RF && rx + 1 < RF &&
                (unsigned)(gy + 1) < (unsigned)Hc && (unsigned)(gx + 1) < (unsigned)Wc)
                e[4] = eclip(dot9(a, pf + (RF + 1) * FSTR));
        }
        float* __restrict__ ed = sEw + idx * 5;
        ed[0] = e[0]; ed[1] = e[1]; ed[2] = e[2]; ed[3] = e[3]; ed[4] = e[4];
    }
    __syncthreads();

    // ------- Phase 2b: deg -> dinv gather + sig load over 34x34, pack float4 -------
    for (int idx = tid; idx < RD * RD; idx += NTHREADS) {
        const int ly = idx / RD;
        const int lx = idx - ly * RD;
        const int gy = y0 - 1 + ly;
        const int gx = x0 - 1 + lx;
        const bool inb = ((unsigned)gy < (unsigned)Hc) && ((unsigned)gx < (unsigned)Wc);
        const int r = (ly + 1) * RF + (lx + 1);  // region coords (offset -2 space)

        float dinv = 0.f;
        if (inb) {
            const float* __restrict__ ep = sEw + r * 5;
            float deg = ep[0] + ep[1] + ep[2] + ep[3] + ep[4];  // self,E,SW,S,SE
            deg += sEw[(r - RF - 1) * 5 + 4];  // NW  = SE of (ry-1,rx-1)
            deg += sEw[(r - RF)     * 5 + 3];  // N   = S  of (ry-1,rx)
            deg += sEw[(r - RF + 1) * 5 + 2];  // NE  = SW of (ry-1,rx+1)
            deg += sEw[(r - 1)      * 5 + 1];  // W   = E  of (ry,rx-1)
            dinv = rsqrtf(deg);                // deg >= 1 when inb (self edge)
        }
        const int p = gy * Wc + gx;
        float4 sd;
        sd.x = inb ? __ldg(sigbg + p)            : 0.f;
        sd.y = inb ? __ldg(sigbg + Nn + p)       : 0.f;
        sd.z = inb ? __ldg(sigbg + 2 * Nn + p)   : 0.f;
        sd.w = dinv;
        sSD[idx] = sd;
    }
    __syncthreads();

    // ---------------- Phase 3: normalized aggregation + output ----------------
    float* __restrict__ outbg = out + (size_t)bg * Cc * Nn;
    for (int idx = tid; idx < TILE * TILE; idx += NTHREADS) {
        const int ly = idx >> 5;
        const int lx = idx & 31;
        const int r = (ly + 2) * RF + (lx + 2);   // region coords
        const int d = (ly + 1) * RD + (lx + 1);   // RD coords

        float ewv[9];
        {
            const float* __restrict__ ep = sEw + r * 5;
            ewv[4] = ep[0]; ewv[5] = ep[1]; ewv[6] = ep[2]; ewv[7] = ep[3]; ewv[8] = ep[4];
            ewv[0] = sEw[(r - RF - 1) * 5 + 4];
            ewv[1] = sEw[(r - RF)     * 5 + 3];
            ewv[2] = sEw[(r - RF + 1) * 5 + 2];
            ewv[3] = sEw[(r - 1)      * 5 + 1];
        }

        const float4 ctr = sSD[d];
        const float dp = ctr.w;
        float a0 = 0.f, a1 = 0.f, a2 = 0.f;
        #pragma unroll
        for (int t = 0; t < 9; t++) {
            const int dy = t / 3 - 1;
            const int dx = t % 3 - 1;
            const float4 nb = (t == 4) ? ctr : sSD[d + dy * RD + dx];
            const float w = dp * ewv[t] * nb.w;
            a0 = fmaf(nb.x, w, a0);
            a1 = fmaf(nb.y, w, a1);
            a2 = fmaf(nb.z, w, a2);
        }
        const int p = (y0 + ly) * Wc + (x0 + lx);
        outbg[p]          = ctr.x - a0;
        outbg[Nn + p]     = ctr.y - a1;
        outbg[2 * Nn + p] = ctr.z - a2;
    }
}

extern "C" void kernel_launch(void* const* d_in, const int* in_sizes, int n_in,
                              void* d_out, int out_size) {
    const float* img = (const float*)d_in[0];  // (B,G,F,H,W)
    const float* sig = (const float*)d_in[1];  // (B,G,C,H,W)
    const float* M   = (const float*)d_in[2];  // (G,F,F)
    float* out = (float*)d_out;

    cudaFuncSetAttribute(glr_fused_kernel,
                         cudaFuncAttributeMaxDynamicSharedMemorySize, SMEM_BYTES);
    cudaMemcpyToSymbolAsync(cM, M, Gc * Fc * Fc * sizeof(float), 0,
                            cudaMemcpyDeviceToDevice, 0);

    dim3 grid(Wc / TILE, Hc / TILE, Bc * Gc);
    glr_fused_kernel<<<grid, NTHREADS, SMEM_BYTES>>>(img, sig, out);
}

// round 4
// speedup vs baseline: 1.5248x; 1.0976x over previous
#include <cuda_runtime.h>
#include <math.h>

// Problem constants (fixed by the reference)
constexpr int Hc = 512, Wc = 512;
constexpr int Bc = 2, Gc = 4, Fc = 9, Cc = 3;
constexpr int Nn = Hc * Wc;

// Tiling
constexpr int TILE = 32;           // output tile
constexpr int RF   = TILE + 4;     // 36: fM + ew region (2-pixel halo), offset -2
constexpr int RD   = TILE + 2;     // 34: dinv/sig region (1-pixel halo), offset -1
constexpr int FSTR = 9;            // per-pixel stride for fM (9 coprime 32: conflict-free scalar LDS)

constexpr int NTHREADS = 512;

// SMEM layout (floats).  sF is dead after phase 2a; sSD aliases it.
constexpr int OFF_EW = 0;
constexpr int SZ_EW  = RF * RF * 5;        // 6480 floats (5 dirs: self,E,SW,S,SE)
constexpr int OFF_U  = OFF_EW + SZ_EW;     // union region (16B aligned: 25920B)
constexpr int SZ_F   = RF * RF * FSTR;     // 11664 floats
constexpr int SZ_SD  = RD * RD * 4;        // 4624 floats (float4: sig0,sig1,sig2,dinv) - aliases sF
constexpr int SM_FLOATS = OFF_U + SZ_F;    // 18144
constexpr int SMEM_BYTES = SM_FLOATS * 4;  // 72576 B -> 3 blocks/SM

__constant__ float cM[Gc * Fc * Fc];

__device__ __forceinline__ float dot9s(const float a[9], const float* __restrict__ q) {
    float s = a[0] * q[0];
    s = fmaf(a[1], q[1], s);
    s = fmaf(a[2], q[2], s);
    s = fmaf(a[3], q[3], s);
    s = fmaf(a[4], q[4], s);
    s = fmaf(a[5], q[5], s);
    s = fmaf(a[6], q[6], s);
    s = fmaf(a[7], q[7], s);
    s = fmaf(a[8], q[8], s);
    return s;
}

__device__ __forceinline__ float eclip(float s) {
    return __expf(fminf(fmaxf(s, -10.f), 10.f));
}

__global__ void __launch_bounds__(NTHREADS, 3)
glr_fused_kernel(const float* __restrict__ img,
                 const float* __restrict__ sig,
                 float* __restrict__ out)
{
    extern __shared__ float sm[];
    float*  __restrict__ sEw = sm + OFF_EW;
    float*  __restrict__ sF  = sm + OFF_U;
    float4* __restrict__ sSD = reinterpret_cast<float4*>(sm + OFF_U);  // aliases sF (sF dead by then)

    const int tid = threadIdx.x;
    const int bg  = blockIdx.z;
    const int g   = bg & (Gc - 1);
    const int x0  = blockIdx.x * TILE;
    const int y0  = blockIdx.y * TILE;

    const float* __restrict__ imgbg = img + (size_t)bg * Fc * Nn;
    const float* __restrict__ sigbg = sig + (size_t)bg * Cc * Nn;
    const float* __restrict__ m     = cM + g * 81;

    // ---------------- Phase 1: fM over 36x36 region (low-register form) ----------------
    for (int idx = tid; idx < RF * RF; idx += NTHREADS) {
        const int ry = idx / RF;
        const int rx = idx - ry * RF;
        const int gy = y0 - 2 + ry;
        const int gx = x0 - 2 + rx;
        float* __restrict__ dst = sF + idx * FSTR;
        if ((unsigned)gy < (unsigned)Hc && (unsigned)gx < (unsigned)Wc) {
            const int p = gy * Wc + gx;
            float acc[9] = {0.f, 0.f, 0.f, 0.f, 0.f, 0.f, 0.f, 0.f, 0.f};
            float ss = 0.f;
            #pragma unroll
            for (int f = 0; f < 9; f++) {
                const float x = __ldg(imgbg + (size_t)f * Nn + p);
                ss = fmaf(x, x, ss);
                #pragma unroll
                for (int v = 0; v < 9; v++) acc[v] = fmaf(x, m[f * 9 + v], acc[v]);
            }
            const float inv = rsqrtf(fmaxf(ss, 1e-24f));
            #pragma unroll
            for (int v = 0; v < 9; v++) dst[v] = acc[v] * inv;
        } else {
            #pragma unroll
            for (int v = 0; v < 9; v++) dst[v] = 0.f;
        }
    }
    __syncthreads();

    // ------- Phase 2a: 5-direction ew (self,E,SW,S,SE) over rows 0..34 -------
    // ew(p,q)=ew(q,p): N/W dirs recovered by transposed reads. Row 35 is never read -> skip.
    for (int idx = tid; idx < (RF - 1) * RF; idx += NTHREADS) {
        const int ry = idx / RF;
        const int rx = idx - ry * RF;
        const int gy = y0 - 2 + ry;
        const int gx = x0 - 2 + rx;
        float* __restrict__ ed = sEw + idx * 5;

        if (((unsigned)gy < (unsigned)Hc) && ((unsigned)gx < (unsigned)Wc)) {
            const float* __restrict__ pf = sF + idx * FSTR;
            float a[9];
            #pragma unroll
            for (int f = 0; f < 9; f++) a[f] = pf[f];

            // self
            float s = a[0] * a[0];
            #pragma unroll
            for (int f = 1; f < 9; f++) s = fmaf(a[f], a[f], s);
            ed[0] = eclip(s);
            // E (0,+1)
            ed[1] = (rx + 1 < RF && (unsigned)(gx + 1) < (unsigned)Wc)
                    ? eclip(dot9s(a, pf + FSTR)) : 0.f;
            // SW (+1,-1)
            ed[2] = (rx - 1 >= 0 &&
                     (unsigned)(gy + 1) < (unsigned)Hc && (unsigned)(gx - 1) < (unsigned)Wc)
                    ? eclip(dot9s(a, pf + (RF - 1) * FSTR)) : 0.f;
            // S (+1,0)
            ed[3] = ((unsigned)(gy + 1) < (unsigned)Hc)
                    ? eclip(dot9s(a, pf + RF * FSTR)) : 0.f;
            // SE (+1,+1)
            ed[4] = (rx + 1 < RF &&
                     (unsigned)(gy + 1) < (unsigned)Hc && (unsigned)(gx + 1) < (unsigned)Wc)
                    ? eclip(dot9s(a, pf + (RF + 1) * FSTR)) : 0.f;
        } else {
            ed[0] = 0.f; ed[1] = 0.f; ed[2] = 0.f; ed[3] = 0.f; ed[4] = 0.f;
        }
    }
    __syncthreads();

    // ------- Phase 2b: deg -> dinv gather + sig load over 34x34, pack float4 -------
    // NOTE: sSD aliases sF; sF is fully consumed by phase 2a.
    for (int idx = tid; idx < RD * RD; idx += NTHREADS) {
        const int ly = idx / RD;
        const int lx = idx - ly * RD;
        const int gy = y0 - 1 + ly;
        const int gx = x0 - 1 + lx;
        const bool inb = ((unsigned)gy < (unsigned)Hc) && ((unsigned)gx < (unsigned)Wc);
        const int r = (ly + 1) * RF + (lx + 1);  // region coords (offset -2 space)

        float dinv = 0.f;
        if (inb) {
            const float* __restrict__ ep = sEw + r * 5;
            float deg = ep[0] + ep[1] + ep[2] + ep[3] + ep[4];  // self,E,SW,S,SE
            deg += sEw[(r - RF - 1) * 5 + 4];  // NW  = SE of (ry-1,rx-1)
            deg += sEw[(r - RF)     * 5 + 3];  // N   = S  of (ry-1,rx)
            deg += sEw[(r - RF + 1) * 5 + 2];  // NE  = SW of (ry-1,rx+1)
            deg += sEw[(r - 1)      * 5 + 1];  // W   = E  of (ry,rx-1)
            dinv = rsqrtf(deg);                // deg >= 1 when inb (self edge)
        }
        const int p = gy * Wc + gx;
        float4 sd;
        sd.x = inb ? __ldg(sigbg + p)          : 0.f;
        sd.y = inb ? __ldg(sigbg + Nn + p)     : 0.f;
        sd.z = inb ? __ldg(sigbg + 2 * Nn + p) : 0.f;
        sd.w = dinv;
        sSD[idx] = sd;
    }
    __syncthreads();

    // ---------------- Phase 3: normalized aggregation + output ----------------
    float* __restrict__ outbg = out + (size_t)bg * Cc * Nn;
    for (int idx = tid; idx < TILE * TILE; idx += NTHREADS) {
        const int ly = idx >> 5;
        const int lx = idx & 31;
        const int r = (ly + 2) * RF + (lx + 2);   // region coords
        const int d = (ly + 1) * RD + (lx + 1);   // RD coords

        const float4 ctr = sSD[d];
        const float dp = ctr.w;
        float a0 = 0.f, a1 = 0.f, a2 = 0.f;

        // t: 0=NW 1=N 2=NE 3=W 4=self 5=E 6=SW 7=S 8=SE  (symmetric transposed fetches for 0..3)
        {
            // NW
            float4 nb = sSD[d - RD - 1];
            float w = dp * sEw[(r - RF - 1) * 5 + 4] * nb.w;
            a0 = fmaf(nb.x, w, a0); a1 = fmaf(nb.y, w, a1); a2 = fmaf(nb.z, w, a2);
            // N
            nb = sSD[d - RD];
            w = dp * sEw[(r - RF) * 5 + 3] * nb.w;
            a0 = fmaf(nb.x, w, a0); a1 = fmaf(nb.y, w, a1); a2 = fmaf(nb.z, w, a2);
            // NE
            nb = sSD[d - RD + 1];
            w = dp * sEw[(r - RF + 1) * 5 + 2] * nb.w;
            a0 = fmaf(nb.x, w, a0); a1 = fmaf(nb.y, w, a1); a2 = fmaf(nb.z, w, a2);
            // W
            nb = sSD[d - 1];
            w = dp * sEw[(r - 1) * 5 + 1] * nb.w;
            a0 = fmaf(nb.x, w, a0); a1 = fmaf(nb.y, w, a1); a2 = fmaf(nb.z, w, a2);
            // self
            w = dp * sEw[r * 5 + 0] * dp;
            a0 = fmaf(ctr.x, w, a0); a1 = fmaf(ctr.y, w, a1); a2 = fmaf(ctr.z, w, a2);
            // E
            nb = sSD[d + 1];
            w = dp * sEw[r * 5 + 1] * nb.w;
            a0 = fmaf(nb.x, w, a0); a1 = fmaf(nb.y, w, a1); a2 = fmaf(nb.z, w, a2);
            // SW
            nb = sSD[d + RD - 1];
            w = dp * sEw[r * 5 + 2] * nb.w;
            a0 = fmaf(nb.x, w, a0); a1 = fmaf(nb.y, w, a1); a2 = fmaf(nb.z, w, a2);
            // S
            nb = sSD[d + RD];
            w = dp * sEw[r * 5 + 3] * nb.w;
            a0 = fmaf(nb.x, w, a0); a1 = fmaf(nb.y, w, a1); a2 = fmaf(nb.z, w, a2);
            // SE
            nb = sSD[d + RD + 1];
            w = dp * sEw[r * 5 + 4] * nb.w;
            a0 = fmaf(nb.x, w, a0); a1 = fmaf(nb.y, w, a1); a2 = fmaf(nb.z, w, a2);
        }

        const int p = (y0 + ly) * Wc + (x0 + lx);
        outbg[p]          = ctr.x - a0;
        outbg[Nn + p]     = ctr.y - a1;
        outbg[2 * Nn + p] = ctr.z - a2;
    }
}

extern "C" void kernel_launch(void* const* d_in, const int* in_sizes, int n_in,
                              void* d_out, int out_size) {
    const float* img = (const float*)d_in[0];  // (B,G,F,H,W)
    const float* sig = (const float*)d_in[1];  // (B,G,C,H,W)
    const float* M   = (const float*)d_in[2];  // (G,F,F)
    float* out = (float*)d_out;

    cudaFuncSetAttribute(glr_fused_kernel,
                         cudaFuncAttributeMaxDynamicSharedMemorySize, SMEM_BYTES);
    cudaMemcpyToSymbolAsync(cM, M, Gc * Fc * Fc * sizeof(float), 0,
                            cudaMemcpyDeviceToDevice, 0);

    dim3 grid(Wc / TILE, Hc / TILE, Bc * Gc);
    glr_fused_kernel<<<grid, NTHREADS, SMEM_BYTES>>>(img, sig, out);
}

// round 5
// speedup vs baseline: 1.5759x; 1.0335x over previous
#include <cuda_runtime.h>
#include <math.h>

// Problem constants (fixed by the reference)
constexpr int Hc = 512, Wc = 512;
constexpr int Bc = 2, Gc = 4, Fc = 9, Cc = 3;
constexpr int Nn = Hc * Wc;

// Tiling
constexpr int TILE = 32;           // output tile
constexpr int RF   = TILE + 4;     // 36: fM + ew region (2-pixel halo), offset -2
constexpr int RD   = TILE + 2;     // 34: dinv/sig region (1-pixel halo), offset -1
constexpr int FSTR = 9;            // per-pixel stride for fM (9 coprime 32: conflict-free scalar LDS)

constexpr int NTHREADS = 512;

// SMEM layout (floats).  sF is dead after phase 2a; sSD aliases it.
constexpr int OFF_EW = 0;
constexpr int SZ_EW  = RF * RF * 5;          // 6480 floats (5 dirs: self,E,SW,S,SE)
constexpr int OFF_U  = OFF_EW + SZ_EW;       // union region (byte off 25920, 16B aligned)
constexpr int SZ_F   = RF * RF * FSTR + 12;  // 11676 (12-float pad: unconditional region-edge reads)
constexpr int SM_FLOATS = OFF_U + SZ_F;      // 18156
constexpr int SMEM_BYTES = SM_FLOATS * 4;    // 72624 B -> 3 blocks/SM

// Pair-packed multiM: per (g,f): pairs (c0,c1)(c2,c3)(c4,c5)(c6,c7)(c8,0)
__constant__ unsigned long long cMp[Gc * Fc * 5];
__device__   unsigned long long g_packM[Gc * Fc * 5];

__device__ __forceinline__ unsigned long long pk2(float lo, float hi) {
    unsigned long long r;
    asm("mov.b64 %0, {%1, %2};" : "=l"(r) : "f"(lo), "f"(hi));
    return r;
}
__device__ __forceinline__ void upk2(float& lo, float& hi, unsigned long long v) {
    asm("mov.b64 {%0, %1}, %2;" : "=f"(lo), "=f"(hi) : "l"(v));
}
__device__ __forceinline__ unsigned long long ffma2(unsigned long long a,
                                                    unsigned long long b,
                                                    unsigned long long c) {
    unsigned long long d;
    asm("fma.rn.f32x2 %0, %1, %2, %3;" : "=l"(d) : "l"(a), "l"(b), "l"(c));
    return d;
}
__device__ __forceinline__ unsigned long long fmul2(unsigned long long a,
                                                    unsigned long long b) {
    unsigned long long d;
    asm("mul.rn.f32x2 %0, %1, %2;" : "=l"(d) : "l"(a), "l"(b));
    return d;
}

__global__ void repack_kernel(const float* __restrict__ M) {
    int i = threadIdx.x;
    if (i < Gc * Fc * 5) {
        int g = i / 45, r = i % 45, f = r / 5, v = r % 5;
        float lo = M[g * 81 + f * 9 + 2 * v];
        float hi = (2 * v + 1 < 9) ? M[g * 81 + f * 9 + 2 * v + 1] : 0.f;
        g_packM[i] = pk2(lo, hi);
    }
}

__device__ __forceinline__ float dot9s(const float a[9], const float* __restrict__ q) {
    float s = a[0] * q[0];
    s = fmaf(a[1], q[1], s);
    s = fmaf(a[2], q[2], s);
    s = fmaf(a[3], q[3], s);
    s = fmaf(a[4], q[4], s);
    s = fmaf(a[5], q[5], s);
    s = fmaf(a[6], q[6], s);
    s = fmaf(a[7], q[7], s);
    s = fmaf(a[8], q[8], s);
    return s;
}

__device__ __forceinline__ float eclip(float s) {
    return __expf(fminf(fmaxf(s, -10.f), 10.f));
}

// Packed-FMA feature transform: load 9 img floats at pixel p, normalize, apply M (packed),
// store 9 floats to dst. Per-element fma order identical to scalar version.
__device__ __forceinline__ void compute_fm(const float* __restrict__ imgbg, int p,
                                           const unsigned long long* __restrict__ mp,
                                           float* __restrict__ dst) {
    unsigned long long a0 = 0ull, a1 = 0ull, a2 = 0ull, a3 = 0ull, a4 = 0ull;
    float ss = 0.f;
    #pragma unroll
    for (int f = 0; f < 9; f++) {
        const float x = __ldg(imgbg + (size_t)f * Nn + p);
        ss = fmaf(x, x, ss);
        const unsigned long long xx = pk2(x, x);
        a0 = ffma2(xx, mp[f * 5 + 0], a0);
        a1 = ffma2(xx, mp[f * 5 + 1], a1);
        a2 = ffma2(xx, mp[f * 5 + 2], a2);
        a3 = ffma2(xx, mp[f * 5 + 3], a3);
        a4 = ffma2(xx, mp[f * 5 + 4], a4);
    }
    const float inv = rsqrtf(fmaxf(ss, 1e-24f));
    const unsigned long long ii = pk2(inv, inv);
    float lo, hi;
    upk2(lo, hi, fmul2(a0, ii)); dst[0] = lo; dst[1] = hi;
    upk2(lo, hi, fmul2(a1, ii)); dst[2] = lo; dst[3] = hi;
    upk2(lo, hi, fmul2(a2, ii)); dst[4] = lo; dst[5] = hi;
    upk2(lo, hi, fmul2(a3, ii)); dst[6] = lo; dst[7] = hi;
    upk2(lo, hi, fmul2(a4, ii)); dst[8] = lo;
}

__global__ void __launch_bounds__(NTHREADS, 3)
glr_fused_kernel(const float* __restrict__ img,
                 const float* __restrict__ sig,
                 float* __restrict__ out)
{
    extern __shared__ float sm[];
    float*  __restrict__ sEw = sm + OFF_EW;
    float*  __restrict__ sF  = sm + OFF_U;
    float4* __restrict__ sSD = reinterpret_cast<float4*>(sm + OFF_U);  // aliases sF

    const int tid = threadIdx.x;
    const int bg  = blockIdx.z;
    const int g   = bg & (Gc - 1);
    const int x0  = blockIdx.x * TILE;
    const int y0  = blockIdx.y * TILE;
    // interior: whole 36x36 region (offset -2) inside the image
    const bool interior = (blockIdx.x >= 1) && (blockIdx.x <= 14) &&
                          (blockIdx.y >= 1) && (blockIdx.y <= 14);

    const float* __restrict__ imgbg = img + (size_t)bg * Fc * Nn;
    const float* __restrict__ sigbg = sig + (size_t)bg * Cc * Nn;
    const unsigned long long* __restrict__ mp = cMp + g * 45;

    // ---------------- Phase 1: fM over 36x36 region ----------------
    if (interior) {
        const int pbase = (y0 - 2) * Wc + (x0 - 2);
        for (int idx = tid; idx < RF * RF; idx += NTHREADS) {
            const int ry = idx / RF;
            const int rx = idx - ry * RF;
            compute_fm(imgbg, pbase + ry * Wc + rx, mp, sF + idx * FSTR);
        }
    } else {
        for (int idx = tid; idx < RF * RF; idx += NTHREADS) {
            const int ry = idx / RF;
            const int rx = idx - ry * RF;
            const int gy = y0 - 2 + ry;
            const int gx = x0 - 2 + rx;
            float* __restrict__ dst = sF + idx * FSTR;
            if ((unsigned)gy < (unsigned)Hc && (unsigned)gx < (unsigned)Wc) {
                compute_fm(imgbg, gy * Wc + gx, mp, dst);
            } else {
                #pragma unroll
                for (int v = 0; v < 9; v++) dst[v] = 0.f;
            }
        }
    }
    __syncthreads();

    // ------- Phase 2a: 5-direction ew (self,E,SW,S,SE) over rows 0..34 -------
    // ew(p,q)=ew(q,p): N/W dirs recovered by transposed reads. Row 35 never read -> skip.
    if (interior) {
        // No predicates: region-edge out-of-window reads land in valid smem (incl. 12-float
        // pad) and produce finite values at slots that are provably never consumed.
        for (int idx = tid; idx < (RF - 1) * RF; idx += NTHREADS) {
            const float* __restrict__ pf = sF + idx * FSTR;
            float a[9];
            #pragma unroll
            for (int f = 0; f < 9; f++) a[f] = pf[f];
            float s = a[0] * a[0];
            #pragma unroll
            for (int f = 1; f < 9; f++) s = fmaf(a[f], a[f], s);
            float* __restrict__ ed = sEw + idx * 5;
            ed[0] = eclip(s);
            ed[1] = eclip(dot9s(a, pf + FSTR));              // E
            ed[2] = eclip(dot9s(a, pf + (RF - 1) * FSTR));   // SW
            ed[3] = eclip(dot9s(a, pf + RF * FSTR));         // S
            ed[4] = eclip(dot9s(a, pf + (RF + 1) * FSTR));   // SE
        }
    } else {
        for (int idx = tid; idx < (RF - 1) * RF; idx += NTHREADS) {
            const int ry = idx / RF;
            const int rx = idx - ry * RF;
            const int gy = y0 - 2 + ry;
            const int gx = x0 - 2 + rx;
            float* __restrict__ ed = sEw + idx * 5;
            if (((unsigned)gy < (unsigned)Hc) && ((unsigned)gx < (unsigned)Wc)) {
                const float* __restrict__ pf = sF + idx * FSTR;
                float a[9];
                #pragma unroll
                for (int f = 0; f < 9; f++) a[f] = pf[f];
                float s = a[0] * a[0];
                #pragma unroll
                for (int f = 1; f < 9; f++) s = fmaf(a[f], a[f], s);
                ed[0] = eclip(s);
                ed[1] = (rx + 1 < RF && (unsigned)(gx + 1) < (unsigned)Wc)
                        ? eclip(dot9s(a, pf + FSTR)) : 0.f;
                ed[2] = (rx - 1 >= 0 &&
                         (unsigned)(gy + 1) < (unsigned)Hc && (unsigned)(gx - 1) < (unsigned)Wc)
                        ? eclip(dot9s(a, pf + (RF - 1) * FSTR)) : 0.f;
                ed[3] = ((unsigned)(gy + 1) < (unsigned)Hc)
                        ? eclip(dot9s(a, pf + RF * FSTR)) : 0.f;
                ed[4] = (rx + 1 < RF &&
                         (unsigned)(gy + 1) < (unsigned)Hc && (unsigned)(gx + 1) < (unsigned)Wc)
                        ? eclip(dot9s(a, pf + (RF + 1) * FSTR)) : 0.f;
            } else {
                ed[0] = 0.f; ed[1] = 0.f; ed[2] = 0.f; ed[3] = 0.f; ed[4] = 0.f;
            }
        }
    }
    __syncthreads();

    // ------- Phase 2b: deg -> dinv gather + sig load over 34x34, pack float4 -------
    // NOTE: sSD aliases sF; sF is fully consumed by phase 2a.
    if (interior) {
        const int pbase = (y0 - 1) * Wc + (x0 - 1);
        for (int idx = tid; idx < RD * RD; idx += NTHREADS) {
            const int ly = idx / RD;
            const int lx = idx - ly * RD;
            const int r = (ly + 1) * RF + (lx + 1);
            const float* __restrict__ ep = sEw + r * 5;
            float deg = ep[0] + ep[1] + ep[2] + ep[3] + ep[4];
            deg += sEw[(r - RF - 1) * 5 + 4];  // NW = SE of up-left
            deg += sEw[(r - RF)     * 5 + 3];  // N  = S  of up
            deg += sEw[(r - RF + 1) * 5 + 2];  // NE = SW of up-right
            deg += sEw[(r - 1)      * 5 + 1];  // W  = E  of left
            const int p = pbase + ly * Wc + lx;
            float4 sd;
            sd.x = __ldg(sigbg + p);
            sd.y = __ldg(sigbg + Nn + p);
            sd.z = __ldg(sigbg + 2 * Nn + p);
            sd.w = rsqrtf(deg);
            sSD[idx] = sd;
        }
    } else {
        for (int idx = tid; idx < RD * RD; idx += NTHREADS) {
            const int ly = idx / RD;
            const int lx = idx - ly * RD;
            const int gy = y0 - 1 + ly;
            const int gx = x0 - 1 + lx;
            const bool inb = ((unsigned)gy < (unsigned)Hc) && ((unsigned)gx < (unsigned)Wc);
            const int r = (ly + 1) * RF + (lx + 1);
            float dinv = 0.f;
            if (inb) {
                const float* __restrict__ ep = sEw + r * 5;
                float deg = ep[0] + ep[1] + ep[2] + ep[3] + ep[4];
                deg += sEw[(r - RF - 1) * 5 + 4];
                deg += sEw[(r - RF)     * 5 + 3];
                deg += sEw[(r - RF + 1) * 5 + 2];
                deg += sEw[(r - 1)      * 5 + 1];
                dinv = rsqrtf(deg);
            }
            const int p = gy * Wc + gx;
            float4 sd;
            sd.x = inb ? __ldg(sigbg + p)          : 0.f;
            sd.y = inb ? __ldg(sigbg + Nn + p)     : 0.f;
            sd.z = inb ? __ldg(sigbg + 2 * Nn + p) : 0.f;
            sd.w = dinv;
            sSD[idx] = sd;
        }
    }
    __syncthreads();

    // ---------------- Phase 3: normalized aggregation + output ----------------
    float* __restrict__ outbg = out + (size_t)bg * Cc * Nn;
    for (int idx = tid; idx < TILE * TILE; idx += NTHREADS) {
        const int ly = idx >> 5;
        const int lx = idx & 31;
        const int r = (ly + 2) * RF + (lx + 2);   // region coords
        const int d = (ly + 1) * RD + (lx + 1);   // RD coords

        const float4 ctr = sSD[d];
        const float dp = ctr.w;
        float a0 = 0.f, a1 = 0.f, a2 = 0.f;

        // NW
        float4 nb = sSD[d - RD - 1];
        float w = dp * sEw[(r - RF - 1) * 5 + 4] * nb.w;
        a0 = fmaf(nb.x, w, a0); a1 = fmaf(nb.y, w, a1); a2 = fmaf(nb.z, w, a2);
        // N
        nb = sSD[d - RD];
        w = dp * sEw[(r - RF) * 5 + 3] * nb.w;
        a0 = fmaf(nb.x, w, a0); a1 = fmaf(nb.y, w, a1); a2 = fmaf(nb.z, w, a2);
        // NE
        nb = sSD[d - RD + 1];
        w = dp * sEw[(r - RF + 1) * 5 + 2] * nb.w;
        a0 = fmaf(nb.x, w, a0); a1 = fmaf(nb.y, w, a1); a2 = fmaf(nb.z, w, a2);
        // W
        nb = sSD[d - 1];
        w = dp * sEw[(r - 1) * 5 + 1] * nb.w;
        a0 = fmaf(nb.x, w, a0); a1 = fmaf(nb.y, w, a1); a2 = fmaf(nb.z, w, a2);
        // self
        w = dp * sEw[r * 5 + 0] * dp;
        a0 = fmaf(ctr.x, w, a0); a1 = fmaf(ctr.y, w, a1); a2 = fmaf(ctr.z, w, a2);
        // E
        nb = sSD[d + 1];
        w = dp * sEw[r * 5 + 1] * nb.w;
        a0 = fmaf(nb.x, w, a0); a1 = fmaf(nb.y, w, a1); a2 = fmaf(nb.z, w, a2);
        // SW
        nb = sSD[d + RD - 1];
        w = dp * sEw[r * 5 + 2] * nb.w;
        a0 = fmaf(nb.x, w, a0); a1 = fmaf(nb.y, w, a1); a2 = fmaf(nb.z, w, a2);
        // S
        nb = sSD[d + RD];
        w = dp * sEw[r * 5 + 3] * nb.w;
        a0 = fmaf(nb.x, w, a0); a1 = fmaf(nb.y, w, a1); a2 = fmaf(nb.z, w, a2);
        // SE
        nb = sSD[d + RD + 1];
        w = dp * sEw[r * 5 + 4] * nb.w;
        a0 = fmaf(nb.x, w, a0); a1 = fmaf(nb.y, w, a1); a2 = fmaf(nb.z, w, a2);

        const int p = (y0 + ly) * Wc + (x0 + lx);
        outbg[p]          = ctr.x - a0;
        outbg[Nn + p]     = ctr.y - a1;
        outbg[2 * Nn + p] = ctr.z - a2;
    }
}

extern "C" void kernel_launch(void* const* d_in, const int* in_sizes, int n_in,
                              void* d_out, int out_size) {
    const float* img = (const float*)d_in[0];  // (B,G,F,H,W)
    const float* sig = (const float*)d_in[1];  // (B,G,C,H,W)
    const float* M   = (const float*)d_in[2];  // (G,F,F)
    float* out = (float*)d_out;

    cudaFuncSetAttribute(glr_fused_kernel,
                         cudaFuncAttributeMaxDynamicSharedMemorySize, SMEM_BYTES);

    // Repack multiM into pair-packed layout, then stage into __constant__.
    repack_kernel<<<1, 192>>>(M);
    void* packed_ptr = nullptr;
    cudaGetSymbolAddress(&packed_ptr, g_packM);
    cudaMemcpyToSymbolAsync(cMp, packed_ptr, Gc * Fc * 5 * sizeof(unsigned long long),
                            0, cudaMemcpyDeviceToDevice, 0);

    dim3 grid(Wc / TILE, Hc / TILE, Bc * Gc);
    glr_fused_kernel<<<grid, NTHREADS, SMEM_BYTES>>>(img, sig, out);
}